// round 5
// baseline (speedup 1.0000x reference)
#include <cuda_runtime.h>
#include <cuda_bf16.h>
#include <math.h>

// Problem constants (inputs/targets: 8192 x 2048 fp32)
#define NROWS 8192
#define NCOLS 2048
#define LAMB  0.1

// Scratch: per-row squared error
__device__ float g_err[NROWS];

// ---------------------------------------------------------------------------
// Kernel 1: err[row] = sum_d (x[row,d]-t[row,d])^2   (HBM roofline)
// ---------------------------------------------------------------------------
__global__ __launch_bounds__(256) void row_sqerr_kernel(
    const float4* __restrict__ x, const float4* __restrict__ t)
{
    const int row = blockIdx.x;
    const float4* xr = x + (size_t)row * (NCOLS / 4);
    const float4* tr = t + (size_t)row * (NCOLS / 4);

    float acc = 0.0f;
    #pragma unroll
    for (int c = threadIdx.x; c < NCOLS / 4; c += 256) {
        float4 a = __ldcg(&xr[c]);
        float4 b = __ldcg(&tr[c]);
        float d0 = a.x - b.x;
        float d1 = a.y - b.y;
        float d2 = a.z - b.z;
        float d3 = a.w - b.w;
        acc += d0 * d0 + d1 * d1 + d2 * d2 + d3 * d3;
    }

    #pragma unroll
    for (int off = 16; off > 0; off >>= 1)
        acc += __shfl_down_sync(0xFFFFFFFFu, acc, off);

    __shared__ float warp_sums[8];
    int lane = threadIdx.x & 31;
    int wid  = threadIdx.x >> 5;
    if (lane == 0) warp_sums[wid] = acc;
    __syncthreads();

    if (wid == 0) {
        float v = (lane < 8) ? warp_sums[lane] : 0.0f;
        #pragma unroll
        for (int off = 4; off > 0; off >>= 1)
            v += __shfl_down_sync(0xFFFFFFFFu, v, off);
        if (lane == 0) g_err[row] = v;
    }
}

// ---------------------------------------------------------------------------
// Bitonic helpers
// ---------------------------------------------------------------------------
__device__ __forceinline__ void cmpswap(float& a, float& b, bool up)
{
    float lo = fminf(a, b);
    float hi = fmaxf(a, b);
    a = up ? lo : hi;
    b = up ? hi : lo;
}

// Intra-thread substage with compile-time J (keeps v[] in registers).
// uniform=true: direction upT for all 32 elems (k >= 32).
// uniform=false: direction per element: ((e & kmask) == 0)  (k <= 16).
template<int J>
__device__ __forceinline__ void intra_stage(float v[32], int kmask,
                                            bool uniform, bool upT)
{
    #pragma unroll
    for (int e = 0; e < 32; e++)
        if ((e & J) == 0) {
            bool up = uniform ? upT : ((e & kmask) == 0);
            cmpswap(v[e], v[e + J], up);
        }
}

__device__ __forceinline__ void shfl_stage(float v[32], int d, bool keep_min)
{
    #pragma unroll
    for (int e = 0; e < 32; e++) {
        float p = __shfl_xor_sync(0xFFFFFFFFu, v[e], d);
        v[e] = keep_min ? fminf(v[e], p) : fmaxf(v[e], p);
    }
}

// ---------------------------------------------------------------------------
// Kernel 2: ONE block, 256 threads, 32 elems/thread in registers.
// Full bitonic sort of g_err[8192]:
//   k = 2..16  : fully intra-thread (per-element direction)
//   k = 32..8192: j>=1024 via smem (6 iters total), j=512..32 via shfl_xor,
//                 j=16..1 intra-thread (uniform direction per thread)
// Then finalize (fp64 scan of (sum,sumsq), h(k) argmin) fused in-register.
// ---------------------------------------------------------------------------
__global__ __launch_bounds__(256) void sort_finalize_kernel(float* __restrict__ out)
{
    __shared__ float  s[8192];       // 32 KB, q-major float4 layout
    __shared__ double s_w1[8], s_w2[8];
    __shared__ float  s_bh[8];
    __shared__ int    s_bk[8];
    __shared__ double s_bp[8];

    const int t  = threadIdx.x;
    const int li = 32 * t;           // global index of first owned element
    const int N  = NROWS;
    float4* s4 = reinterpret_cast<float4*>(s);

    // load 32 consecutive elements
    float v[32];
    {
        const float4* g4 = reinterpret_cast<const float4*>(g_err);
        #pragma unroll
        for (int q = 0; q < 8; q++) {
            float4 a = g4[t * 8 + q];
            v[4*q+0] = a.x; v[4*q+1] = a.y; v[4*q+2] = a.z; v[4*q+3] = a.w;
        }
    }

    // ---- k = 2, 4, 8, 16 : fully intra-thread ----
    intra_stage<1>(v, 2, false, false);

    intra_stage<2>(v, 4, false, false);
    intra_stage<1>(v, 4, false, false);

    intra_stage<4>(v, 8, false, false);
    intra_stage<2>(v, 8, false, false);
    intra_stage<1>(v, 8, false, false);

    intra_stage<8>(v, 16, false, false);
    intra_stage<4>(v, 16, false, false);
    intra_stage<2>(v, 16, false, false);
    intra_stage<1>(v, 16, false, false);

    // ---- k = 32 .. 8192 ----
    for (int k = 32; k <= 8192; k <<= 1) {
        const bool upT = ((li & k) == 0);

        // smem substages: j = k/2 .. 1024   (only k >= 2048; 6 iters total)
        for (int j = k >> 1; j >= 1024; j >>= 1) {
            #pragma unroll
            for (int q = 0; q < 8; q++)
                s4[q * 256 + t] = make_float4(v[4*q], v[4*q+1], v[4*q+2], v[4*q+3]);
            __syncthreads();
            int pt = t ^ (j >> 5);                       // partner thread
            bool keep_min = (upT == ((t & (j >> 5)) == 0));
            #pragma unroll
            for (int q = 0; q < 8; q++) {
                float4 p = s4[q * 256 + pt];
                v[4*q+0] = keep_min ? fminf(v[4*q+0], p.x) : fmaxf(v[4*q+0], p.x);
                v[4*q+1] = keep_min ? fminf(v[4*q+1], p.y) : fmaxf(v[4*q+1], p.y);
                v[4*q+2] = keep_min ? fminf(v[4*q+2], p.z) : fmaxf(v[4*q+2], p.z);
                v[4*q+3] = keep_min ? fminf(v[4*q+3], p.w) : fmaxf(v[4*q+3], p.w);
            }
            __syncthreads();
        }

        // shfl substages: j = min(k/2, 512) .. 32   (lane xor d = j/32 <= 16)
        int jstart = (k >> 1) < 512 ? (k >> 1) : 512;
        for (int j = jstart; j >= 32; j >>= 1) {
            int d = j >> 5;
            bool keep_min = (upT == ((t & d) == 0));
            shfl_stage(v, d, keep_min);
        }

        // intra substages: j = 16 .. 1 (uniform direction)
        intra_stage<16>(v, k, true, upT);
        intra_stage<8> (v, k, true, upT);
        intra_stage<4> (v, k, true, upT);
        intra_stage<2> (v, k, true, upT);
        intra_stage<1> (v, k, true, upT);
    }

    // ---- Finalize: v[0..31] = sorted elements [32t, 32t+32) ascending ----
    const int lane = t & 31;
    const int wid  = t >> 5;

    double l1 = 0.0, l2 = 0.0;
    #pragma unroll
    for (int i = 0; i < 32; i++) {
        double d = (double)v[i];
        l1 += d;
        l2 += d * d;
    }

    // warp inclusive scan of (l1, l2)
    double i1 = l1, i2 = l2;
    #pragma unroll
    for (int off = 1; off < 32; off <<= 1) {
        double a = __shfl_up_sync(0xFFFFFFFFu, i1, off);
        double b = __shfl_up_sync(0xFFFFFFFFu, i2, off);
        if (lane >= off) { i1 += a; i2 += b; }
    }
    if (lane == 31) { s_w1[wid] = i1; s_w2[wid] = i2; }
    __syncthreads();

    if (wid == 0) {
        double a1 = (lane < 8) ? s_w1[lane] : 0.0;
        double a2 = (lane < 8) ? s_w2[lane] : 0.0;
        #pragma unroll
        for (int off = 1; off < 8; off <<= 1) {
            double x = __shfl_up_sync(0xFFFFFFFFu, a1, off);
            double y = __shfl_up_sync(0xFFFFFFFFu, a2, off);
            if (lane >= off) { a1 += x; a2 += y; }
        }
        if (lane < 8) { s_w1[lane] = a1; s_w2[lane] = a2; }
    }
    __syncthreads();

    double base1 = (wid == 0) ? 0.0 : s_w1[wid - 1];
    double base2 = (wid == 0) ? 0.0 : s_w2[wid - 1];
    double tot1 = s_w1[7];
    double tot2 = s_w2[7];
    double p1 = base1 + i1 - l1;     // exclusive prefix before this chunk
    double p2 = base2 + i2 - l2;

    const double ts = tot2 - tot1 * tot1 / (double)N;
    const float invTS = (float)(1.0 / ts);

    float  bestH = INFINITY;
    int    bestK = 0x7FFFFFFF;
    double bestP1 = 0.0;
    #pragma unroll
    for (int i = 0; i < 32; i++) {
        double d = (double)v[i];
        p1 += d;
        p2 += d * d;
        int k = li + i + 1;
        if (k <= N - 1) {
            double cin  = (double)k;
            double cout = (double)(N - k);
            double r1   = tot1 - p1;
            double num_in  = p2 * cin - p1 * p1;            // within_in  * cin
            double num_out = (tot2 - p2) * cout - r1 * r1;  // within_out * cout
            float h = ((float)num_in  / (float)cin +
                       (float)num_out / (float)cout) * invTS;
            if (h < bestH) { bestH = h; bestK = k; bestP1 = p1; }
        }
    }

    // warp argmin (h, then k for first-index tiebreak)
    #pragma unroll
    for (int off = 16; off > 0; off >>= 1) {
        float  h2 = __shfl_down_sync(0xFFFFFFFFu, bestH, off);
        int    k2 = __shfl_down_sync(0xFFFFFFFFu, bestK, off);
        double q2 = __shfl_down_sync(0xFFFFFFFFu, bestP1, off);
        if (h2 < bestH || (h2 == bestH && k2 < bestK)) {
            bestH = h2; bestK = k2; bestP1 = q2;
        }
    }
    if (lane == 0) { s_bh[wid] = bestH; s_bk[wid] = bestK; s_bp[wid] = bestP1; }
    __syncthreads();

    if (wid == 0 && lane == 0) {
        float  h = s_bh[0];
        int    k = s_bk[0];
        double q = s_bp[0];
        #pragma unroll
        for (int w = 1; w < 8; w++) {
            if (s_bh[w] < h || (s_bh[w] == h && s_bk[w] < k)) {
                h = s_bh[w]; k = s_bk[w]; q = s_bp[w];
            }
        }
        double obj = q / (double)k;
        out[0] = (float)(obj + LAMB * (double)h);
    }
}

// ---------------------------------------------------------------------------
extern "C" void kernel_launch(void* const* d_in, const int* in_sizes, int n_in,
                              void* d_out, int out_size)
{
    const float4* x = (const float4*)d_in[0];
    const float4* t = (const float4*)d_in[1];
    float* out = (float*)d_out;

    row_sqerr_kernel<<<NROWS, 256>>>(x, t);
    sort_finalize_kernel<<<1, 256>>>(out);
}

// round 6
// speedup vs baseline: 1.2406x; 1.2406x over previous
#include <cuda_runtime.h>
#include <cuda_bf16.h>
#include <math.h>
#include <stdint.h>

// Problem constants (inputs/targets: 8192 x 2048 fp32)
#define NROWS 8192
#define NCOLS 2048
#define LAMB  0.1

#define CLN  4      // CTAs per cluster
#define WPC  2048   // elements per CTA window
#define THR  256    // threads per CTA
#define E    8      // elements per thread (in registers)

// Scratch: per-row squared error
__device__ float g_err[NROWS];

// ---------------------------------------------------------------------------
// Kernel 1: err[row] = sum_d (x[row,d]-t[row,d])^2   (HBM roofline, ~24us)
// ---------------------------------------------------------------------------
__global__ __launch_bounds__(256) void row_sqerr_kernel(
    const float4* __restrict__ x, const float4* __restrict__ t)
{
    const int row = blockIdx.x;
    const float4* xr = x + (size_t)row * (NCOLS / 4);
    const float4* tr = t + (size_t)row * (NCOLS / 4);

    float acc = 0.0f;
    #pragma unroll
    for (int c = threadIdx.x; c < NCOLS / 4; c += 256) {
        float4 a = __ldcg(&xr[c]);
        float4 b = __ldcg(&tr[c]);
        float d0 = a.x - b.x;
        float d1 = a.y - b.y;
        float d2 = a.z - b.z;
        float d3 = a.w - b.w;
        acc += d0 * d0 + d1 * d1 + d2 * d2 + d3 * d3;
    }

    #pragma unroll
    for (int off = 16; off > 0; off >>= 1)
        acc += __shfl_down_sync(0xFFFFFFFFu, acc, off);

    __shared__ float warp_sums[8];
    int lane = threadIdx.x & 31;
    int wid  = threadIdx.x >> 5;
    if (lane == 0) warp_sums[wid] = acc;
    __syncthreads();

    if (wid == 0) {
        float v = (lane < 8) ? warp_sums[lane] : 0.0f;
        #pragma unroll
        for (int off = 4; off > 0; off >>= 1)
            v += __shfl_down_sync(0xFFFFFFFFu, v, off);
        if (lane == 0) g_err[row] = v;
    }
}

// ---------------------------------------------------------------------------
// Cluster / DSMEM helpers
// ---------------------------------------------------------------------------
__device__ __forceinline__ uint32_t smem_u32(const void* p)
{
    uint32_t a;
    asm("{ .reg .u64 t; cvta.to.shared.u64 t, %1; cvt.u32.u64 %0, t; }"
        : "=r"(a) : "l"(p));
    return a;
}
__device__ __forceinline__ uint32_t my_ctarank()
{
    uint32_t r;
    asm("mov.u32 %0, %%cluster_ctarank;" : "=r"(r));
    return r;
}
__device__ __forceinline__ uint32_t mapa_u32(uint32_t a, uint32_t rank)
{
    uint32_t r;
    asm("mapa.shared::cluster.u32 %0, %1, %2;" : "=r"(r) : "r"(a), "r"(rank));
    return r;
}
__device__ __forceinline__ float4 ld_dsm_f4(uint32_t a)
{
    float4 v;
    asm volatile("ld.shared::cluster.v4.f32 {%0,%1,%2,%3}, [%4];"
                 : "=f"(v.x), "=f"(v.y), "=f"(v.z), "=f"(v.w) : "r"(a));
    return v;
}
__device__ __forceinline__ double ld_dsm_f64(uint32_t a)
{
    unsigned long long u;
    asm volatile("ld.shared::cluster.b64 %0, [%1];" : "=l"(u) : "r"(a));
    return __longlong_as_double((long long)u);
}
__device__ __forceinline__ uint32_t ld_dsm_b32(uint32_t a)
{
    uint32_t u;
    asm volatile("ld.shared::cluster.b32 %0, [%1];" : "=r"(u) : "r"(a));
    return u;
}
#define CLUSTER_SYNC() do { \
    asm volatile("barrier.cluster.arrive.aligned;" ::: "memory"); \
    asm volatile("barrier.cluster.wait.aligned;"   ::: "memory"); \
} while (0)

// ---------------------------------------------------------------------------
// Bitonic helpers (E = 8 elems/thread)
// ---------------------------------------------------------------------------
__device__ __forceinline__ void cmpswap(float& a, float& b, bool up)
{
    float lo = fminf(a, b);
    float hi = fmaxf(a, b);
    a = up ? lo : hi;
    b = up ? hi : lo;
}

template<int J>
__device__ __forceinline__ void intra8(float v[E], int kmask, bool uniform, bool upT)
{
    #pragma unroll
    for (int e = 0; e < E; e++)
        if ((e & J) == 0) {
            bool up = uniform ? upT : ((e & kmask) == 0);
            cmpswap(v[e], v[e | J], up);
        }
}

__device__ __forceinline__ void combine8(float v[E], float4 p0, float4 p1, bool keep_min)
{
    float p[E] = {p0.x, p0.y, p0.z, p0.w, p1.x, p1.y, p1.z, p1.w};
    #pragma unroll
    for (int e = 0; e < E; e++)
        v[e] = keep_min ? fminf(v[e], p[e]) : fmaxf(v[e], p[e]);
}

__device__ __forceinline__ void shfl_stage8(float v[E], int d, bool keep_min)
{
    #pragma unroll
    for (int e = 0; e < E; e++) {
        float p = __shfl_xor_sync(0xFFFFFFFFu, v[e], d);
        v[e] = keep_min ? fminf(v[e], p) : fmaxf(v[e], p);
    }
}

// In-CTA smem substage (256 <= j <= 1024). Layout: s4[t]=v[0..3], s4[256+t]=v[4..7]
__device__ __forceinline__ void smem_stage(float v[E], float4* s4, int t, int j, bool upT)
{
    s4[t]       = make_float4(v[0], v[1], v[2], v[3]);
    s4[256 + t] = make_float4(v[4], v[5], v[6], v[7]);
    __syncthreads();
    int pt = t ^ (j >> 3);
    float4 p0 = s4[pt];
    float4 p1 = s4[256 + pt];
    bool keep_min = (upT == ((t & (j >> 3)) == 0));
    combine8(v, p0, p1, keep_min);
    __syncthreads();
}

// Cross-CTA substage (j >= WPC): exchange full window with partner CTA via DSMEM.
__device__ __forceinline__ void dsmem_stage(float v[E], float4* s4, uint32_t sbase,
                                            int t, uint32_t prank, bool keep_min)
{
    s4[t]       = make_float4(v[0], v[1], v[2], v[3]);
    s4[256 + t] = make_float4(v[4], v[5], v[6], v[7]);
    __syncthreads();
    CLUSTER_SYNC();                               // all windows written
    uint32_t pa = mapa_u32(sbase, prank);
    float4 p0 = ld_dsm_f4(pa + (uint32_t)t * 16u);
    float4 p1 = ld_dsm_f4(pa + (uint32_t)(256 + t) * 16u);
    combine8(v, p0, p1, keep_min);
    CLUSTER_SYNC();                               // all reads done before reuse of s
}

// ---------------------------------------------------------------------------
// Kernel 2: cluster of 4 CTAs x 256 threads; each CTA owns 2048 elements
// (8/thread in registers). Full bitonic sort + fused finalize.
// ---------------------------------------------------------------------------
__global__ __launch_bounds__(THR) __cluster_dims__(CLN, 1, 1)
void sort_finalize_cluster(float* __restrict__ out)
{
    __shared__ float  s[WPC];                 // 8 KB window
    __shared__ double s_w1[8], s_w2[8];
    __shared__ double s_tot[2];               // this CTA's (sum, sumsq)
    __shared__ double s_ct1[CLN], s_ct2[CLN]; // gathered CTA totals
    __shared__ float  s_bh[8];
    __shared__ int    s_bk[8];
    __shared__ double s_bp[8];
    __shared__ float  s_cbh;                  // CTA-best (exported via DSMEM)
    __shared__ int    s_cbk;
    __shared__ double s_cbp;

    const int t = threadIdx.x;
    const uint32_t rank = my_ctarank();
    const int gi = (int)rank * WPC + E * t;   // global index of first owned elem
    const int N = NROWS;
    float4* s4 = reinterpret_cast<float4*>(s);
    const uint32_t sbase = smem_u32(s);

    // load 8 consecutive elements
    float v[E];
    {
        const float4* g4 = reinterpret_cast<const float4*>(g_err);
        #pragma unroll
        for (int q = 0; q < 2; q++) {
            float4 a = g4[rank * (WPC / 4) + 2 * t + q];
            v[4*q+0] = a.x; v[4*q+1] = a.y; v[4*q+2] = a.z; v[4*q+3] = a.w;
        }
    }

    // ---- k = 2, 4, 8 : fully intra-thread (per-element direction) ----
    intra8<1>(v, 2, false, false);

    intra8<2>(v, 4, false, false);
    intra8<1>(v, 4, false, false);

    intra8<4>(v, 8, false, false);
    intra8<2>(v, 8, false, false);
    intra8<1>(v, 8, false, false);

    // ---- k = 16 .. 2048 : local to this CTA ----
    for (int k = 16; k <= 2048; k <<= 1) {
        const bool upT = ((gi & k) == 0);

        for (int j = k >> 1; j >= 256; j >>= 1)        // smem (k>=512 only)
            smem_stage(v, s4, t, j, upT);

        int js = (k >> 1) < 128 ? (k >> 1) : 128;
        for (int j = js; j >= 8; j >>= 1) {            // shfl (d = j/8 <= 16)
            int d = j >> 3;
            shfl_stage8(v, d, (upT == ((t & d) == 0)));
        }

        intra8<4>(v, k, true, upT);
        intra8<2>(v, k, true, upT);
        intra8<1>(v, k, true, upT);
    }

    // ---- k = 4096 : one cross-CTA substage (j=2048), rest local ----
    {
        const bool upT = ((gi & 4096) == 0);
        dsmem_stage(v, s4, sbase, t, rank ^ 1u, (upT == ((gi & 2048) == 0)));
        for (int j = 1024; j >= 256; j >>= 1) smem_stage(v, s4, t, j, upT);
        for (int j = 128; j >= 8; j >>= 1) {
            int d = j >> 3;
            shfl_stage8(v, d, (upT == ((t & d) == 0)));
        }
        intra8<4>(v, 4096, true, upT);
        intra8<2>(v, 4096, true, upT);
        intra8<1>(v, 4096, true, upT);
    }

    // ---- k = 8192 : two cross-CTA substages (j=4096, 2048), rest local ----
    {
        const bool upT = true;   // (gi & 8192) == 0 for all
        dsmem_stage(v, s4, sbase, t, rank ^ 2u, ((gi & 4096) == 0));
        dsmem_stage(v, s4, sbase, t, rank ^ 1u, ((gi & 2048) == 0));
        for (int j = 1024; j >= 256; j >>= 1) smem_stage(v, s4, t, j, upT);
        for (int j = 128; j >= 8; j >>= 1) {
            int d = j >> 3;
            shfl_stage8(v, d, (upT == ((t & d) == 0)));
        }
        intra8<4>(v, 8192, true, upT);
        intra8<2>(v, 8192, true, upT);
        intra8<1>(v, 8192, true, upT);
    }

    // ---- Finalize: v[0..7] = sorted elements [gi, gi+8) ascending ----
    const int lane = t & 31;
    const int wid  = t >> 5;

    double l1 = 0.0, l2 = 0.0;
    #pragma unroll
    for (int i = 0; i < E; i++) {
        double d = (double)v[i];
        l1 += d;
        l2 += d * d;
    }

    // warp inclusive scan of (l1, l2)
    double i1 = l1, i2 = l2;
    #pragma unroll
    for (int off = 1; off < 32; off <<= 1) {
        double a = __shfl_up_sync(0xFFFFFFFFu, i1, off);
        double b = __shfl_up_sync(0xFFFFFFFFu, i2, off);
        if (lane >= off) { i1 += a; i2 += b; }
    }
    if (lane == 31) { s_w1[wid] = i1; s_w2[wid] = i2; }
    __syncthreads();

    if (wid == 0) {
        double a1 = (lane < 8) ? s_w1[lane] : 0.0;
        double a2 = (lane < 8) ? s_w2[lane] : 0.0;
        #pragma unroll
        for (int off = 1; off < 8; off <<= 1) {
            double x = __shfl_up_sync(0xFFFFFFFFu, a1, off);
            double y = __shfl_up_sync(0xFFFFFFFFu, a2, off);
            if (lane >= off) { a1 += x; a2 += y; }
        }
        if (lane < 8) { s_w1[lane] = a1; s_w2[lane] = a2; }
    }
    __syncthreads();

    // Export this CTA's totals, gather all 4 CTAs' totals via DSMEM.
    if (t == 0) { s_tot[0] = s_w1[7]; s_tot[1] = s_w2[7]; }
    __syncthreads();
    CLUSTER_SYNC();
    if (t < CLN) {
        uint32_t pa = mapa_u32(smem_u32(s_tot), (uint32_t)t);
        s_ct1[t] = ld_dsm_f64(pa);
        s_ct2[t] = ld_dsm_f64(pa + 8u);
    }
    __syncthreads();

    double tot1 = 0.0, tot2 = 0.0, cb1 = 0.0, cb2 = 0.0;
    #pragma unroll
    for (int r = 0; r < CLN; r++) {
        tot1 += s_ct1[r];
        tot2 += s_ct2[r];
        if (r < (int)rank) { cb1 += s_ct1[r]; cb2 += s_ct2[r]; }
    }

    double wbase1 = (wid == 0) ? 0.0 : s_w1[wid - 1];
    double wbase2 = (wid == 0) ? 0.0 : s_w2[wid - 1];
    double p1 = cb1 + wbase1 + i1 - l1;   // exclusive prefix before this chunk
    double p2 = cb2 + wbase2 + i2 - l2;

    const double ts = tot2 - tot1 * tot1 / (double)N;
    const float invTS = (float)(1.0 / ts);

    float  bestH = INFINITY;
    int    bestK = 0x7FFFFFFF;
    double bestP1 = 0.0;
    #pragma unroll
    for (int i = 0; i < E; i++) {
        double d = (double)v[i];
        p1 += d;
        p2 += d * d;
        int k = gi + i + 1;
        if (k <= N - 1) {
            double cin  = (double)k;
            double cout = (double)(N - k);
            double r1   = tot1 - p1;
            double num_in  = p2 * cin - p1 * p1;            // within_in  * cin
            double num_out = (tot2 - p2) * cout - r1 * r1;  // within_out * cout
            float h = ((float)num_in  / (float)cin +
                       (float)num_out / (float)cout) * invTS;
            if (h < bestH) { bestH = h; bestK = k; bestP1 = p1; }
        }
    }

    // warp argmin (h, then k for first-index tiebreak)
    #pragma unroll
    for (int off = 16; off > 0; off >>= 1) {
        float  h2 = __shfl_down_sync(0xFFFFFFFFu, bestH, off);
        int    k2 = __shfl_down_sync(0xFFFFFFFFu, bestK, off);
        double q2 = __shfl_down_sync(0xFFFFFFFFu, bestP1, off);
        if (h2 < bestH || (h2 == bestH && k2 < bestK)) {
            bestH = h2; bestK = k2; bestP1 = q2;
        }
    }
    if (lane == 0) { s_bh[wid] = bestH; s_bk[wid] = bestK; s_bp[wid] = bestP1; }
    __syncthreads();

    if (t == 0) {
        float  h = s_bh[0];
        int    k = s_bk[0];
        double q = s_bp[0];
        #pragma unroll
        for (int w = 1; w < 8; w++)
            if (s_bh[w] < h || (s_bh[w] == h && s_bk[w] < k)) {
                h = s_bh[w]; k = s_bk[w]; q = s_bp[w];
            }
        s_cbh = h; s_cbk = k; s_cbp = q;
    }
    __syncthreads();
    CLUSTER_SYNC();                                   // all CTA-bests exported

    if (rank == 0 && t == 0) {
        float  h = INFINITY;
        int    k = 0x7FFFFFFF;
        double q = 0.0;
        uint32_t ah = smem_u32(&s_cbh);
        uint32_t ak = smem_u32(&s_cbk);
        uint32_t ap = smem_u32(&s_cbp);
        #pragma unroll
        for (int r = 0; r < CLN; r++) {
            float  h2 = __uint_as_float(ld_dsm_b32(mapa_u32(ah, (uint32_t)r)));
            int    k2 = (int)ld_dsm_b32(mapa_u32(ak, (uint32_t)r));
            double q2 = ld_dsm_f64(mapa_u32(ap, (uint32_t)r));
            if (h2 < h || (h2 == h && k2 < k)) { h = h2; k = k2; q = q2; }
        }
        double obj = q / (double)k;
        out[0] = (float)(obj + LAMB * (double)h);
    }
    CLUSTER_SYNC();   // keep all CTAs resident until rank 0 finished reading
}

// ---------------------------------------------------------------------------
extern "C" void kernel_launch(void* const* d_in, const int* in_sizes, int n_in,
                              void* d_out, int out_size)
{
    const float4* x = (const float4*)d_in[0];
    const float4* t = (const float4*)d_in[1];
    float* out = (float*)d_out;

    row_sqerr_kernel<<<NROWS, 256>>>(x, t);
    sort_finalize_cluster<<<CLN, THR>>>(out);
}